// round 14
// baseline (speedup 1.0000x reference)
#include <cuda_runtime.h>
#include <cstdint>
#include <cstddef>

#define K_   512
#define D_   64
#define N_   262144
#define BM   128
#define THREADS 256
#define CAP  1024   // candidate list capacity

// ---- smem byte offsets (vq_main) ----
#define SMO_A     0            // [128][132B] bf16 z tile (32 u32 + 1 pad per row)
#define SMO_B     16896        // [512][128B] bf16 codebook, XOR-swizzled rows
#define SMO_BSQ   82432        // [512] f32
#define SMO_ASQ   84480        // [128] f32
#define SMO_DLT   84992        // [128] f32
#define SMO_CNT   85504        // counter + pad
#define SMO_LIST  85520        // [1024] u32 candidates (p<<16|k)
#define SMO_BEST  89616        // [128] u64 packed (dist_bits<<32)|k
#define SMO_SIDX  90640        // [128] i32 winner
#define SMO_OVF   91152        // [128] i32 overflow flags
#define SMEM_MAIN 91664        // x2 = 183,328 B -> occupancy 2

// ---- device scratch ----
__device__ float g_bcs[K_];
__device__ float g_bes[K_ * D_];
__device__ float g_bsq[K_];
__device__ unsigned g_bbf[K_ * D_ / 2];  // codebook bf16 pairs
__device__ unsigned g_cmaxbits;

// ---- helpers ----
__device__ __forceinline__ unsigned pack_bf16x2(float hi, float lo) {
    unsigned r;
    asm("cvt.rn.bf16x2.f32 %0, %1, %2;" : "=r"(r) : "f"(hi), "f"(lo));
    return r;
}
__device__ __forceinline__ void mma16816(float* c, const unsigned* a, const unsigned* b) {
    asm volatile(
        "mma.sync.aligned.m16n8k16.row.col.f32.bf16.bf16.f32 "
        "{%0,%1,%2,%3}, {%4,%5,%6,%7}, {%8,%9}, {%0,%1,%2,%3};"
        : "+f"(c[0]), "+f"(c[1]), "+f"(c[2]), "+f"(c[3])
        : "r"(a[0]), "r"(a[1]), "r"(a[2]), "r"(a[3]), "r"(b[0]), "r"(b[1]));
}
// monotone f32 -> u32 order map (handles negatives)
__device__ __forceinline__ unsigned fflip(float x) {
    unsigned b = __float_as_uint(x);
    return b ^ (unsigned)(((int)b >> 31) | 0x80000000);
}
// sorted top-4 (ascending) branchless insert
__device__ __forceinline__ void top4_update(unsigned t[4], unsigned v) {
    unsigned n0 = min(t[0], v);
    unsigned n1 = min(t[1], max(t[0], v));
    unsigned n2 = min(t[2], max(t[1], v));
    unsigned n3 = min(t[3], max(t[2], v));
    t[0] = n0; t[1] = n1; t[2] = n2; t[3] = n3;
}

// exact reference-rounded distance + lexicographic publish
__device__ __forceinline__ void verify_cand(
    const float* __restrict__ z, const float* __restrict__ cb,
    const float* sasq, const float* sbsq, unsigned long long* sbest,
    int p0, int p, int k)
{
    const float* zr = z + (size_t)(p0 + p) * D_;
    const float* cr = cb + (size_t)k * D_;
    float dot = 0.0f;
#pragma unroll 16
    for (int d = 0; d < D_; ++d) dot = __fmaf_rn(zr[d], cr[d], dot);
    float de = __fadd_rn(__fmaf_rn(-2.0f, dot, sasq[p]), sbsq[k]);
    unsigned long long pk = ((unsigned long long)__float_as_uint(de) << 32) | (unsigned)k;
    atomicMin(&sbest[p], pk);
}

// ---------------- prep ----------------
__global__ void vq_prep(const float* __restrict__ cb) {
    int i = blockIdx.x * blockDim.x + threadIdx.x;
    if (i < K_ * D_) g_bes[i] = 0.0f;
    if (i < K_ * D_ / 2) g_bbf[i] = pack_bf16x2(cb[2 * i + 1], cb[2 * i]);
    if (i < K_) {
        g_bcs[i] = 0.0f;
        const float* row = cb + i * D_;
        float s = 0.0f;  // reference: mul then add, ascending, NO fma
#pragma unroll
        for (int d = 0; d < D_; ++d) s = __fadd_rn(s, __fmul_rn(row[d], row[d]));
        g_bsq[i] = s;
        atomicMax(&g_cmaxbits, __float_as_uint(s));
    }
}

// ---------------- main ----------------
extern __shared__ char smem[];

__global__ void __launch_bounds__(THREADS, 2) vq_main(
    const float* __restrict__ z, const float* __restrict__ cb,
    float* __restrict__ o_zq, float* __restrict__ o_idx, float* __restrict__ o_mind)
{
    const int tid = threadIdx.x;
    const int wid = tid >> 5, lane = tid & 31;
    const int gid = lane >> 2, tig = lane & 3;
    const int p0 = blockIdx.x * BM;

    unsigned* sA  = (unsigned*)(smem + SMO_A);
    unsigned* sB  = (unsigned*)(smem + SMO_B);
    float* sbsq = (float*)(smem + SMO_BSQ);
    float* sasq = (float*)(smem + SMO_ASQ);
    float* sdlt = (float*)(smem + SMO_DLT);
    int*   scnt = (int*)(smem + SMO_CNT);
    unsigned* slist = (unsigned*)(smem + SMO_LIST);
    unsigned long long* sbest = (unsigned long long*)(smem + SMO_BEST);
    int* sidx = (int*)(smem + SMO_SIDX);
    int* sovf = (int*)(smem + SMO_OVF);

    // ---- phase 0: fills + inits ----
    {
        const float2* z2 = (const float2*)(z + (size_t)p0 * D_);
        for (int i = tid; i < BM * 32; i += THREADS) {
            float2 v = z2[i];
            sA[(i >> 5) * 33 + (i & 31)] = pack_bf16x2(v.y, v.x);
        }
        const float4* gb4 = (const float4*)g_bbf;
        for (int i4 = tid; i4 < K_ * 8; i4 += THREADS) {
            int row = i4 >> 3, x4 = (i4 & 7) << 2;
            float4 v = gb4[i4];
            *(float4*)(sB + row * 32 + (x4 ^ ((row & 7) << 2))) = v;
        }
        for (int i = tid; i < K_; i += THREADS) sbsq[i] = g_bsq[i];
    }
    if (tid == 0) scnt[0] = 0;
    if (tid < BM) {
        sbest[tid] = 0xFFFFFFFFFFFFFFFFull;
        sovf[tid] = 0;
        // exact asq: ascending mul+add on original f32 z bits (L1-hot lines)
        const float* zr = z + (size_t)(p0 + tid) * D_;
        float a = 0.0f;
#pragma unroll
        for (int d = 0; d < D_; ++d) a = __fadd_rn(a, __fmul_rn(zr[d], zr[d]));
        sasq[tid] = a;
        float cmax = __uint_as_float(g_cmaxbits);
        float rt = sqrtf(a * cmax);
        sdlt[tid] = 0.03125f * rt + 0.0078125f * (cmax + 2.0f * rt) + 1e-3f;
    }
    __syncthreads();

    // ---- A fragments (points r0 = 16*wid+gid, r1 = r0+8) ----
    unsigned af[4][4];
#pragma unroll
    for (int ks = 0; ks < 4; ++ks) {
        int r0 = (16 * wid + gid) * 33, r1 = (16 * wid + gid + 8) * 33;
        int x = tig + 8 * ks;
        af[ks][0] = sA[r0 + x];
        af[ks][1] = sA[r1 + x];
        af[ks][2] = sA[r0 + x + 4];
        af[ks][3] = sA[r1 + x + 4];
    }

    // ---- GEMM + fused qmin + per-lane top-4 candidates ----
    const int gx = gid << 2;
    float qr0 = 3.4e38f, qr1 = 3.4e38f;
    unsigned t4a[4] = {0xFFFFFFFFu, 0xFFFFFFFFu, 0xFFFFFFFFu, 0xFFFFFFFFu};
    unsigned t4b[4] = {0xFFFFFFFFu, 0xFFFFFFFFu, 0xFFFFFFFFu, 0xFFFFFFFFu};
    for (int nc = 0; nc < 64; nc += 2) {
        float acc[2][4] = {{0.f, 0.f, 0.f, 0.f}, {0.f, 0.f, 0.f, 0.f}};
#pragma unroll
        for (int ks = 0; ks < 4; ++ks) {
#pragma unroll
            for (int u = 0; u < 2; ++u) {
                int crow = ((nc + u) * 8 + gid) * 32;
                int x0 = tig + 8 * ks;
                unsigned b[2];
                b[0] = sB[crow + (x0 ^ gx)];
                b[1] = sB[crow + ((x0 + 4) ^ gx)];
                mma16816(acc[u], af[ks], b);
            }
        }
#pragma unroll
        for (int u = 0; u < 2; ++u) {
            float2 bs = *(const float2*)(sbsq + (nc + u) * 8 + 2 * tig);
            float q0 = __fmaf_rn(-2.0f, acc[u][0], bs.x);
            float q1 = __fmaf_rn(-2.0f, acc[u][1], bs.y);
            float q2 = __fmaf_rn(-2.0f, acc[u][2], bs.x);
            float q3 = __fmaf_rn(-2.0f, acc[u][3], bs.y);
            qr0 = fminf(qr0, fminf(q0, q1));
            qr1 = fminf(qr1, fminf(q2, q3));
            unsigned k0 = (unsigned)(8 * (nc + u) + 2 * tig);
            top4_update(t4a, (fflip(q0) & 0xFFFF0000u) | k0);
            top4_update(t4a, (fflip(q1) & 0xFFFF0000u) | (k0 + 1));
            top4_update(t4b, (fflip(q2) & 0xFFFF0000u) | k0);
            top4_update(t4b, (fflip(q3) & 0xFFFF0000u) | (k0 + 1));
        }
    }
    // butterfly min over the 4-lane group: every lane ends with the group min
    qr0 = fminf(qr0, __shfl_xor_sync(0xFFFFFFFFu, qr0, 1));
    qr0 = fminf(qr0, __shfl_xor_sync(0xFFFFFFFFu, qr0, 2));
    qr1 = fminf(qr1, __shfl_xor_sync(0xFFFFFFFFu, qr1, 1));
    qr1 = fminf(qr1, __shfl_xor_sync(0xFFFFFFFFu, qr1, 2));

    // ---- emit candidates (truncation-conservative), flag overflow ----
    {
        const int r0 = 16 * wid + gid, r1 = r0 + 8;
        float T0 = qr0 + sdlt[r0];
        float T1 = qr1 + sdlt[r1];
        unsigned Tp0 = (fflip(T0) & 0xFFFF0000u) | 0xFFFFu;
        unsigned Tp1 = (fflip(T1) & 0xFFFF0000u) | 0xFFFFu;
#pragma unroll
        for (int j = 0; j < 4; ++j) {
            if (t4a[j] <= Tp0) {
                int slot = atomicAdd(scnt, 1);
                unsigned e = ((unsigned)r0 << 16) | (t4a[j] & 0xFFFFu);
                if (slot < CAP) slist[slot] = e;
                else verify_cand(z, cb, sasq, sbsq, sbest, p0, r0, (int)(t4a[j] & 0xFFFFu));
            }
            if (t4b[j] <= Tp1) {
                int slot = atomicAdd(scnt, 1);
                unsigned e = ((unsigned)r1 << 16) | (t4b[j] & 0xFFFFu);
                if (slot < CAP) slist[slot] = e;
                else verify_cand(z, cb, sasq, sbsq, sbest, p0, r1, (int)(t4b[j] & 0xFFFFu));
            }
        }
        if (t4a[3] <= Tp0) sovf[r0] = 1;   // 4th-best within T: may have missed some
        if (t4b[3] <= Tp1) sovf[r1] = 1;
    }
    __syncthreads();

    // ---- cooperative exact verify ----
    {
        int m = scnt[0]; if (m > CAP) m = CAP;
        for (int ci = tid; ci < m; ci += THREADS) {
            unsigned e = slist[ci];
            verify_cand(z, cb, sasq, sbsq, sbest, p0, (int)(e >> 16), (int)(e & 0xFFFF));
        }
        // overflow sweep: full-512 exact for flagged points (expected: none)
        for (int p = 0; p < BM; ++p) {
            if (sovf[p]) {
                for (int k = tid; k < K_; k += THREADS)
                    verify_cand(z, cb, sasq, sbsq, sbest, p0, p, k);
            }
        }
    }
    __syncthreads();

    // ---- outputs + cluster-size atomic ----
    if (tid < BM) {
        unsigned long long pk = sbest[tid];
        int bi = (int)(pk & 0xFFFFFFFFu);
        o_idx[p0 + tid] = (float)bi;
        o_mind[p0 + tid] = __uint_as_float((unsigned)(pk >> 32));
        sidx[tid] = bi;
        atomicAdd(&g_bcs[bi], 1.0f);
    }
    __syncthreads();

    // ---- z_q_st (z_e + (z_q - z_e), non-fused) + embedding-sum scatter ----
    for (int i = tid; i < BM * D_; i += THREADS) {
        int p = i >> 6, d = i & 63;
        int bi = sidx[p];
        float ze = z[(size_t)p0 * D_ + i];
        float zq = cb[bi * D_ + d];
        o_zq[(size_t)p0 * D_ + i] = __fadd_rn(ze, __fsub_rn(zq, ze));
        atomicAdd(&g_bes[bi * D_ + d], ze);
    }
}

// ---------------- finalize ----------------
__global__ void vq_final(const float* __restrict__ ema_cs, const float* __restrict__ ema_es,
                         float* __restrict__ o_cb, float* __restrict__ o_cs,
                         float* __restrict__ o_es)
{
    int i = blockIdx.x * blockDim.x + threadIdx.x;
    if (i < K_) {
        o_cs[i] = __fadd_rn(__fmul_rn(0.99f, ema_cs[i]), __fmul_rn(0.01f, g_bcs[i]));
    }
    if (i < K_ * D_) {
        int k = i / D_;
        float ncs = __fadd_rn(__fmul_rn(0.99f, ema_cs[k]), __fmul_rn(0.01f, g_bcs[k]));
        float nes = __fadd_rn(__fmul_rn(0.99f, ema_es[i]), __fmul_rn(0.01f, g_bes[i]));
        o_es[i] = nes;
        o_cb[i] = __fdiv_rn(nes, __fadd_rn(ncs, 1e-5f));
    }
}

// ---------------- launcher ----------------
extern "C" void kernel_launch(void* const* d_in, const int* in_sizes, int n_in,
                              void* d_out, int out_size)
{
    const float* z      = (const float*)d_in[0];
    const float* cb     = (const float*)d_in[1];
    const float* ema_cs = (const float*)d_in[2];
    const float* ema_es = (const float*)d_in[3];

    float* out    = (float*)d_out;
    float* o_zq   = out;
    float* o_idx  = o_zq + (size_t)N_ * D_;
    float* o_mind = o_idx + N_;
    float* o_cb   = o_mind + N_;
    float* o_cs   = o_cb + (size_t)K_ * D_;
    float* o_es   = o_cs + K_;

    (void)in_sizes; (void)n_in; (void)out_size;

    vq_prep<<<(K_ * D_ + 255) / 256, 256>>>(cb);

    cudaFuncSetAttribute(vq_main, cudaFuncAttributeMaxDynamicSharedMemorySize, SMEM_MAIN);
    vq_main<<<N_ / BM, THREADS, SMEM_MAIN>>>(z, cb, o_zq, o_idx, o_mind);

    vq_final<<<(K_ * D_ + 255) / 256, 256>>>(ema_cs, ema_es, o_cb, o_cs, o_es);
}

// round 16
// speedup vs baseline: 1.8793x; 1.8793x over previous
#include <cuda_runtime.h>
#include <cstdint>
#include <cstddef>

// Problem constants (fixed by the dataset)
#define K_   512      // num_embeddings
#define D_   64       // embedding_dim
#define N_   262144   // H*W = 512*512
#define BM   128      // points per block
#define KC   128      // codes per chunk
#define NCH  (K_ / KC)
#define THREADS 256
#define ZST  132      // szT row stride in floats (16B aligned)

// ---- device scratch (no allocations allowed) ----
__device__ float g_bcs[K_];                       // batch cluster size accumulator
__device__ float g_bes[K_ * D_];                  // batch embedding sum accumulator
__device__ unsigned long long g_scd[D_ * K_];     // dup (c,c) codes, granule-interleaved per chunk
__device__ float g_bsq[K_];                       // ||c_k||^2

// ---------------- packed f32x2 helpers ----------------
__device__ __forceinline__ unsigned long long pack2(float lo, float hi) {
    unsigned long long r;
    asm("mov.b64 %0, {%1, %2};" : "=l"(r) : "f"(lo), "f"(hi));
    return r;
}
__device__ __forceinline__ void unpack2(unsigned long long v, float& lo, float& hi) {
    asm("mov.b64 {%0, %1}, %2;" : "=f"(lo), "=f"(hi) : "l"(v));
}
__device__ __forceinline__ void fma2(unsigned long long& acc, unsigned long long a,
                                     unsigned long long b) {
    asm("fma.rn.f32x2 %0, %1, %2, %0;" : "+l"(acc) : "l"(a), "l"(b));
}

// ---------------- dummy kernels: pad launch index so ncu's "-s 5 -c 1"
// (skip 5, capture 1) lands exactly on vq_main (launch #5, 0-based, per call) ----
__global__ void vq_pad() {}

// ---------------- prep ----------------
// Layout of g_scd row d, chunk ch (128 consecutive u64):
//   granule g = j*16 + tx  (16B = 2 u64) holds codes {ch*128 + 32j + 2tx, +1}
//   so u64 position = d*K_ + ch*128 + (j*16 + tx)*2 + (k&1)
__global__ void vq_prep(const float* __restrict__ cb) {
    int i = blockIdx.x * blockDim.x + threadIdx.x;
    if (i < K_ * D_) {
        int k = i / D_, d = i % D_;
        float v = cb[i];                       // coalesced read
        int ch = k >> 7;
        int lp = (k & 127) >> 1;               // local pair 0..63
        int tx = lp & 15, j = lp >> 4;
        int pos = d * K_ + ch * 128 + (j * 16 + tx) * 2 + (k & 1);
        g_scd[pos] = pack2(v, v);
        g_bes[i] = 0.0f;
    }
    if (i < K_) {
        g_bcs[i] = 0.0f;
        const float* row = cb + i * D_;
        // reference: jnp.sum(c*c, axis=1) -> mul then add, ascending, NO fma
        float s = 0.0f;
#pragma unroll
        for (int d = 0; d < D_; ++d) s = __fadd_rn(s, __fmul_rn(row[d], row[d]));
        g_bsq[i] = s;
    }
}

// ---------------- main: distances + argmin + z_q_st + inline stats ----------------
extern __shared__ float smem[];

__global__ void __launch_bounds__(THREADS, 2) vq_main(
    const float* __restrict__ z, const float* __restrict__ cb,
    float* __restrict__ o_zq, float* __restrict__ o_idx, float* __restrict__ o_mind)
{
    float* szT = smem;                                  // [D_][ZST]  z tile, d-major
    unsigned long long* scd = (unsigned long long*)(smem + D_ * ZST);  // [D_][KC] interleaved
    float* sbs  = (float*)(scd + D_ * KC);              // [KC] b_sq chunk (chunk-local index)
    float* sasq = sbs + KC;                             // [BM] a_sq per point
    int*   sidx = (int*)(sasq + BM);                    // [BM] winning index
    // reduction arrays alias scd after the last chunk is consumed
    float* redv = (float*)scd;                          // [16][BM]
    int*   redi = (int*)((float*)scd + 16 * BM);        // [16][BM]

    const int tid = threadIdx.x;
    const int tx = tid & 15;           // code lane
    const int ty = tid >> 4;           // point group: points ty*8..ty*8+7 (4 packed pairs)
    const int p0 = blockIdx.x * BM;

    // load z tile transposed: szT[d][p] = z[p][d]
    const float4* zg4 = (const float4*)(z + (size_t)p0 * D_);
    for (int i = tid; i < BM * D_ / 4; i += THREADS) {
        int p = i >> 4, q = i & 15;
        float4 v = zg4[p * 16 + q];
        int d = q * 4;
        szT[(d + 0) * ZST + p] = v.x;
        szT[(d + 1) * ZST + p] = v.y;
        szT[(d + 2) * ZST + p] = v.z;
        szT[(d + 3) * ZST + p] = v.w;
    }
    __syncthreads();

    // a_sq per point: sequential ascending, mul+add (NO fma) — replicates XLA reduction.
    if (tid < BM) {
        float a = 0.0f;
#pragma unroll
        for (int d = 0; d < D_; ++d) {
            float v = szT[d * ZST + tid];
            a = __fadd_rn(a, __fmul_rn(v, v));
        }
        sasq[tid] = a;
    }

    float bestv[8];
    int   besti[8];
#pragma unroll
    for (int p = 0; p < 8; ++p) { bestv[p] = 3.4e38f; besti[p] = 0x7fffffff; }

    for (int ch = 0; ch < NCH; ++ch) {
        if (ch) __syncthreads();  // previous chunk fully consumed
        // copy codebook chunk (dup + interleaved) from global: pure float4 copy
        {
            const float4* gs = (const float4*)g_scd;   // row d = K_/2 float4
            for (int i = tid; i < D_ * KC / 2; i += THREADS) {
                int d = i >> 6, j = i & 63;
                float4 v = gs[d * (K_ / 2) + ch * (KC / 2) + j];
                *((float4*)(scd + d * KC) + j) = v;
            }
            if (tid < KC) sbs[tid] = g_bsq[ch * KC + tid];
        }
        __syncthreads();  // chunk (and on ch==0: sasq) visible

        // dot = sequential ascending-d fma chain; f32x2 lanes = two adjacent points
        unsigned long long acc[8][4];
#pragma unroll
        for (int c = 0; c < 8; ++c)
#pragma unroll
            for (int pp = 0; pp < 4; ++pp) acc[c][pp] = 0ull;

#pragma unroll 4
        for (int d = 0; d < D_; ++d) {
            // 4 point-pairs: 2x LDS.128 (broadcast within warp)
            const ulonglong2* zp2 = (const ulonglong2*)(szT + d * ZST + ty * 8);
            ulonglong2 za = zp2[0], zb = zp2[1];
            unsigned long long zp[4] = { za.x, za.y, zb.x, zb.y };
            // 8 codes as 4 granules at 16B lane stride (conflict-free):
            // granule j at u64 offset d*KC + (j*16 + tx)*2
            const ulonglong2* cg = (const ulonglong2*)(scd + d * KC);
            ulonglong2 c0 = cg[0 * 16 + tx];
            ulonglong2 c1 = cg[1 * 16 + tx];
            ulonglong2 c2 = cg[2 * 16 + tx];
            ulonglong2 c3 = cg[3 * 16 + tx];
            unsigned long long cd[8] = { c0.x, c0.y, c1.x, c1.y,
                                         c2.x, c2.y, c3.x, c3.y };
#pragma unroll
            for (int c = 0; c < 8; ++c)
#pragma unroll
                for (int pp = 0; pp < 4; ++pp) fma2(acc[c][pp], zp[pp], cd[c]);
        }

        // epilogue: dist = fl(fl(asq - 2*dot) + bsq)
        // thread's code (j, e): cidx = ch*128 + 32j + 2tx + e
#pragma unroll
        for (int c = 0; c < 8; ++c) {           // c = j*2 + e
            int j = c >> 1, e = c & 1;
            int lk = 32 * j + 2 * tx + e;       // chunk-local code index
            float bs = sbs[lk];
            int cidx = ch * KC + lk;
#pragma unroll
            for (int pp = 0; pp < 4; ++pp) {
                float lo, hi;
                unpack2(acc[c][pp], lo, hi);
                float a0 = sasq[ty * 8 + 2 * pp];
                float a1 = sasq[ty * 8 + 2 * pp + 1];
                float d0 = __fadd_rn(__fmaf_rn(-2.0f, lo, a0), bs);
                float d1 = __fadd_rn(__fmaf_rn(-2.0f, hi, a1), bs);
                if (d0 < bestv[2 * pp])     { bestv[2 * pp] = d0;     besti[2 * pp] = cidx; }
                if (d1 < bestv[2 * pp + 1]) { bestv[2 * pp + 1] = d1; besti[2 * pp + 1] = cidx; }
            }
        }
    }

    __syncthreads();  // all reads of scd done -> reuse as reduction space
#pragma unroll
    for (int p = 0; p < 8; ++p) {
        redv[tx * BM + ty * 8 + p] = bestv[p];
        redi[tx * BM + ty * 8 + p] = besti[p];
    }
    __syncthreads();

    if (tid < BM) {
        int p = tid;
        float bv = redv[p];
        int bi = redi[p];
#pragma unroll
        for (int t = 1; t < 16; ++t) {
            float v = redv[t * BM + p];
            int ii = redi[t * BM + p];
            if (v < bv || (v == bv && ii < bi)) { bv = v; bi = ii; }
        }
        o_idx[p0 + p]  = (float)bi;
        o_mind[p0 + p] = bv;
        sidx[p] = bi;
        atomicAdd(&g_bcs[bi], 1.0f);
    }
    __syncthreads();

    // z_q_st = z_e + (z_q - z_e), non-fused, mirroring the reference; EMA scatter inline
    for (int i = tid; i < BM * D_; i += THREADS) {
        int p = i >> 6, d = i & 63;
        int bi = sidx[p];
        float ze = szT[d * ZST + p];
        float zq = cb[bi * D_ + d];
        o_zq[(size_t)(p0 + p) * D_ + d] = __fadd_rn(ze, __fsub_rn(zq, ze));
        atomicAdd(&g_bes[bi * D_ + d], ze);
    }
}

// ---------------- finalize: EMA update + new codebook ----------------
__global__ void vq_final(const float* __restrict__ ema_cs, const float* __restrict__ ema_es,
                         float* __restrict__ o_cb, float* __restrict__ o_cs,
                         float* __restrict__ o_es)
{
    int i = blockIdx.x * blockDim.x + threadIdx.x;
    if (i < K_) {
        o_cs[i] = __fadd_rn(__fmul_rn(0.99f, ema_cs[i]), __fmul_rn(0.01f, g_bcs[i]));
    }
    if (i < K_ * D_) {
        int k = i / D_;
        float ncs = __fadd_rn(__fmul_rn(0.99f, ema_cs[k]), __fmul_rn(0.01f, g_bcs[k]));
        float nes = __fadd_rn(__fmul_rn(0.99f, ema_es[i]), __fmul_rn(0.01f, g_bes[i]));
        o_es[i] = nes;
        o_cb[i] = __fdiv_rn(nes, __fadd_rn(ncs, 1e-5f));
    }
}

// ---------------- launcher ----------------
extern "C" void kernel_launch(void* const* d_in, const int* in_sizes, int n_in,
                              void* d_out, int out_size)
{
    const float* z      = (const float*)d_in[0];  // [512,512,64]
    const float* cb     = (const float*)d_in[1];  // [512,64]
    const float* ema_cs = (const float*)d_in[2];  // [512]
    const float* ema_es = (const float*)d_in[3];  // [512,64]

    float* out    = (float*)d_out;
    float* o_zq   = out;                              // N*D
    float* o_idx  = o_zq + (size_t)N_ * D_;           // N
    float* o_mind = o_idx + N_;                       // N
    float* o_cb   = o_mind + N_;                      // K*D
    float* o_cs   = o_cb + (size_t)K_ * D_;           // K
    float* o_es   = o_cs + K_;                        // K*D

    (void)in_sizes; (void)n_in; (void)out_size;

    // launch index (0-based, per call): 0=prep, 1..4=pad, 5=vq_main, 6=final.
    // ncu's "-s 5 -c 1" therefore captures vq_main.
    vq_prep<<<(K_ * D_ + 255) / 256, 256>>>(cb);
    vq_pad<<<1, 32>>>();
    vq_pad<<<1, 32>>>();
    vq_pad<<<1, 32>>>();
    vq_pad<<<1, 32>>>();

    // vq_main smem: szT + scd + sbs + sasq + sidx = 100,864 B
    const size_t smem_main = (size_t)(D_ * ZST) * 4 + (size_t)(D_ * KC) * 8
                           + (size_t)(KC + BM) * 4 + (size_t)BM * 4;
    cudaFuncSetAttribute(vq_main, cudaFuncAttributeMaxDynamicSharedMemorySize,
                         (int)smem_main);
    vq_main<<<N_ / BM, THREADS, smem_main>>>(z, cb, o_zq, o_idx, o_mind);

    vq_final<<<(K_ * D_ + 255) / 256, 256>>>(ema_cs, ema_es, o_cb, o_cs, o_es);
}